// round 17
// baseline (speedup 1.0000x reference)
#include <cuda_runtime.h>
#include <cstdint>

// Shift op: x[32,64,56,56] -> out[32,576,56,56]
// out[n, c*9 + s, y, x] = x[n, c, y + s/3 - 1, x + s%3 - 1], zero-padded.
//
// FINAL kernel (converged over an 11-variant design matrix):
//  - 2 output rows per thread: 4 aligned float4 loads + 8 edge scalars
//    feed 18 independent STG.128 (minimum of the U-shaped amortization
//    curve: 1 row/thread is LSU-issue bound, 4 rows/thread is
//    latency/occupancy bound).
//  - loads: ld.global.nc.L2::cache_hint + fractional evict_last policy
//    (26MB input stays L2-resident across its 9 rereads).
//  - stores: st.global.cs evict-first (231MB write stream doesn't churn L2).
//  - block 256, interleaved store order (best-measured ncu config).
// Measured-neutral-or-worse alternatives: bulk-async staging (single and
// double buffered), 256-bit v8 ld/st, forced-high occupancy, grid-stride,
// plane-sequential global write order, plane-major store order, 4-row
// amortization. The kernel sits at the HBM3e effective write-stream wall
// (~5.1 TB/s for ~90%-write traffic, ~64% of 8 TB/s spec).

#define N_  32
#define C_  64
#define H_  56
#define W_  56
#define W4 (W_ / 4)      // 14
#define H2 (H_ / 2)      // 28 row-pairs

__device__ __forceinline__ uint64_t mk_policy() {
    uint64_t p;
    asm("createpolicy.fractional.L2::evict_last.b64 %0, 1.0;" : "=l"(p));
    return p;
}

__device__ __forceinline__ float4 ldg_el4(const float* p, uint64_t pol) {
    float4 v;
    asm volatile("ld.global.nc.L2::cache_hint.v4.f32 {%0,%1,%2,%3}, [%4], %5;"
                 : "=f"(v.x), "=f"(v.y), "=f"(v.z), "=f"(v.w)
                 : "l"(p), "l"(pol));
    return v;
}
__device__ __forceinline__ float ldg_el1(const float* p, uint64_t pol) {
    float v;
    asm volatile("ld.global.nc.L2::cache_hint.f32 %0, [%1], %2;"
                 : "=f"(v) : "l"(p), "l"(pol));
    return v;
}

__global__ __launch_bounds__(256) void shift_kernel(
    const float* __restrict__ in, float* __restrict__ out, int total)
{
    int idx = blockIdx.x * blockDim.x + threadIdx.x;
    if (idx >= total) return;

    const uint64_t pol = mk_policy();

    // idx -> (nc, y2, x4);  y = 2*y2
    int x4 = idx % W4;
    int t  = idx / W4;
    int y2 = t % H2;
    int nc = t / H2;
    int y  = y2 * 2;

    int x0 = x4 * 4;
    const float* plane = in + (long long)nc * (H_ * W_);

    // rows y-1 .. y+2
    float4 v[4];
    float  lft[4], rgt[4];
    #pragma unroll
    for (int r = 0; r < 4; r++) {
        int sy = y + r - 1;
        if ((unsigned)sy < (unsigned)H_) {
            const float* row = plane + sy * W_;
            v[r]   = ldg_el4(row + x0, pol);
            lft[r] = (x0 > 0)      ? ldg_el1(row + x0 - 1, pol) : 0.f;
            rgt[r] = (x0 + 4 < W_) ? ldg_el1(row + x0 + 4, pol) : 0.f;
        } else {
            v[r]   = make_float4(0.f, 0.f, 0.f, 0.f);
            lft[r] = 0.f;
            rgt[r] = 0.f;
        }
    }

    // out float4 base for (nc, s=0, y, x4)
    float4* obase = reinterpret_cast<float4*>(out)
                    + ((long long)nc * 9) * (H_ * W4) + y * W4 + x4;
    const int sstride = H_ * W4;   // one s-plane in float4s

    #pragma unroll
    for (int dy = 0; dy < 3; dy++) {
        #pragma unroll
        for (int r = 0; r < 2; r++) {
            float4 b = v[dy + r];                               // src row y+r+dy-1
            float4 a = make_float4(lft[dy + r], b.x, b.y, b.z); // dx = 0
            float4 c = make_float4(b.y, b.z, b.w, rgt[dy + r]); // dx = 2
            float4* o = obase + r * W4;
            __stcs(o + (dy * 3 + 0) * sstride, a);
            __stcs(o + (dy * 3 + 1) * sstride, b);
            __stcs(o + (dy * 3 + 2) * sstride, c);
        }
    }
}

extern "C" void kernel_launch(void* const* d_in, const int* in_sizes, int n_in,
                              void* d_out, int out_size) {
    const float* x = (const float*)d_in[0];
    float* out = (float*)d_out;
    int total = N_ * C_ * H2 * W4;   // 802,816 threads
    int threads = 256;
    int blocks = (total + threads - 1) / threads;
    shift_kernel<<<blocks, threads>>>(x, out, total);
}